// round 4
// baseline (speedup 1.0000x reference)
#include <cuda_runtime.h>

// QuantumAutoencoder strip-pool + cos. In: [32768,3,32,32] f32 -> Out: [32768,64] f32.
// Coalesced: float4-slot t (0..255) same position across 3 channels; 4 images per
// block for MLP=12; __ldcs streaming hint (single-touch data).

#define PI_F 3.14159265358979323846f
#define IMGS_PER_BLOCK 4

__global__ void __launch_bounds__(256) qae_kernel(const float4* __restrict__ in,
                                                  float* __restrict__ out) {
    int t = threadIdx.x;                       // 0..255
    int img0 = blockIdx.x * IMGS_PER_BLOCK;

    float4 a[IMGS_PER_BLOCK], b[IMGS_PER_BLOCK], c[IMGS_PER_BLOCK];
    #pragma unroll
    for (int i = 0; i < IMGS_PER_BLOCK; ++i) {
        const float4* p = in + (size_t)(img0 + i) * 768;  // 3*1024/4
        a[i] = __ldcs(p + t);
        b[i] = __ldcs(p + t + 256);
        c[i] = __ldcs(p + t + 512);
    }

    #pragma unroll
    for (int i = 0; i < IMGS_PER_BLOCK; ++i) {
        float v = ((a[i].x + a[i].y) + (a[i].z + a[i].w))
                + ((b[i].x + b[i].y) + (b[i].z + b[i].w))
                + ((c[i].x + c[i].y) + (c[i].z + c[i].w));
        v += __shfl_xor_sync(0xffffffffu, v, 1);
        v += __shfl_xor_sync(0xffffffffu, v, 2);
        if ((t & 3) == 0) {
            float mean = v * (1.0f / 48.0f);
            float ang = mean * (PI_F / 255.0f) - (PI_F * 0.5f);
            out[(size_t)(img0 + i) * 64 + (t >> 2)] = cosf(ang);
        }
    }
}

extern "C" void kernel_launch(void* const* d_in, const int* in_sizes, int n_in,
                              void* d_out, int out_size) {
    const float4* in = (const float4*)d_in[0];
    float* out = (float*)d_out;
    int n_img = in_sizes[0] / (3 * 32 * 32);     // 32768
    int blocks = n_img / IMGS_PER_BLOCK;         // 8192
    qae_kernel<<<blocks, 256>>>(in, out);
}

// round 5
// speedup vs baseline: 1.0482x; 1.0482x over previous
#include <cuda_runtime.h>

// QuantumAutoencoder strip-pool + cos. In: [32768,3,32,32] f32 -> Out: [32768,64] f32.
// R3 structure (2 imgs/block, regs~32, occ~84%) + streaming cache hints only.
// float4-slot t (0..255) is the same spatial position across the 3 channels
// (offsets t, t+256, t+512); patch p = slots 4p..4p+3 -> shfl_xor reduce.

#define PI_F 3.14159265358979323846f
#define IMGS_PER_BLOCK 2

__global__ void __launch_bounds__(256) qae_kernel(const float4* __restrict__ in,
                                                  float* __restrict__ out) {
    int t = threadIdx.x;                       // 0..255
    int img0 = blockIdx.x * IMGS_PER_BLOCK;

    float s[IMGS_PER_BLOCK];
    #pragma unroll
    for (int i = 0; i < IMGS_PER_BLOCK; ++i) {
        const float4* p = in + (size_t)(img0 + i) * 768;  // 3*1024/4
        float4 a = __ldcs(p + t);
        float4 b = __ldcs(p + t + 256);
        float4 c = __ldcs(p + t + 512);
        s[i] = ((a.x + a.y) + (a.z + a.w))
             + ((b.x + b.y) + (b.z + b.w))
             + ((c.x + c.y) + (c.z + c.w));
    }

    #pragma unroll
    for (int i = 0; i < IMGS_PER_BLOCK; ++i) {
        float v = s[i];
        v += __shfl_xor_sync(0xffffffffu, v, 1);
        v += __shfl_xor_sync(0xffffffffu, v, 2);
        if ((t & 3) == 0) {
            float mean = v * (1.0f / 48.0f);
            float ang = mean * (PI_F / 255.0f) - (PI_F * 0.5f);
            __stcs(&out[(size_t)(img0 + i) * 64 + (t >> 2)], cosf(ang));
        }
    }
}

extern "C" void kernel_launch(void* const* d_in, const int* in_sizes, int n_in,
                              void* d_out, int out_size) {
    const float4* in = (const float4*)d_in[0];
    float* out = (float*)d_out;
    int n_img = in_sizes[0] / (3 * 32 * 32);     // 32768
    int blocks = n_img / IMGS_PER_BLOCK;         // 16384
    qae_kernel<<<blocks, 256>>>(in, out);
}

// round 6
// speedup vs baseline: 1.0515x; 1.0031x over previous
#include <cuda_runtime.h>

// QuantumAutoencoder strip-pool + cos. In: [32768,3,32,32] f32 -> Out: [32768,64] f32.
// R3 structure (2 imgs/block, regs~32, occ~84%) + streaming cache hints only.
// float4-slot t (0..255) is the same spatial position across the 3 channels
// (offsets t, t+256, t+512); patch p = slots 4p..4p+3 -> shfl_xor reduce.

#define PI_F 3.14159265358979323846f
#define IMGS_PER_BLOCK 2

__global__ void __launch_bounds__(256) qae_kernel(const float4* __restrict__ in,
                                                  float* __restrict__ out) {
    int t = threadIdx.x;                       // 0..255
    int img0 = blockIdx.x * IMGS_PER_BLOCK;

    float s[IMGS_PER_BLOCK];
    #pragma unroll
    for (int i = 0; i < IMGS_PER_BLOCK; ++i) {
        const float4* p = in + (size_t)(img0 + i) * 768;  // 3*1024/4
        float4 a = __ldcs(p + t);
        float4 b = __ldcs(p + t + 256);
        float4 c = __ldcs(p + t + 512);
        s[i] = ((a.x + a.y) + (a.z + a.w))
             + ((b.x + b.y) + (b.z + b.w))
             + ((c.x + c.y) + (c.z + c.w));
    }

    #pragma unroll
    for (int i = 0; i < IMGS_PER_BLOCK; ++i) {
        float v = s[i];
        v += __shfl_xor_sync(0xffffffffu, v, 1);
        v += __shfl_xor_sync(0xffffffffu, v, 2);
        if ((t & 3) == 0) {
            float mean = v * (1.0f / 48.0f);
            float ang = mean * (PI_F / 255.0f) - (PI_F * 0.5f);
            __stcs(&out[(size_t)(img0 + i) * 64 + (t >> 2)], cosf(ang));
        }
    }
}

extern "C" void kernel_launch(void* const* d_in, const int* in_sizes, int n_in,
                              void* d_out, int out_size) {
    const float4* in = (const float4*)d_in[0];
    float* out = (float*)d_out;
    int n_img = in_sizes[0] / (3 * 32 * 32);     // 32768
    int blocks = n_img / IMGS_PER_BLOCK;         // 16384
    qae_kernel<<<blocks, 256>>>(in, out);
}

// round 7
// speedup vs baseline: 1.0553x; 1.0036x over previous
#include <cuda_runtime.h>

// QuantumAutoencoder strip-pool + cos. In: [32768,3,32,32] f32 -> Out: [32768,64] f32.
// 512-thread blocks, 4 images/block: each block streams 24KB contiguous.
// Thread t: imgLocal = t>>8, slot = t&255; slot is the same spatial position
// across the 3 channels (offsets slot, slot+256, slot+512 in float4 units).
// Patch p = slots 4p..4p+3 -> 2-step shfl_xor reduce over 4 lanes.

#define PI_F 3.14159265358979323846f

__global__ void __launch_bounds__(512) qae_kernel(const float4* __restrict__ in,
                                                  float* __restrict__ out) {
    int t = threadIdx.x;                        // 0..511
    int slot = t & 255;                         // float4 slot within image
    int imgLocal = t >> 8;                      // 0..1
    int img0 = blockIdx.x * 4 + imgLocal;       // this thread covers img0, img0+2

    float s[2];
    #pragma unroll
    for (int i = 0; i < 2; ++i) {
        const float4* p = in + (size_t)(img0 + i * 2) * 768;  // 3*1024/4
        float4 a = __ldcs(p + slot);
        float4 b = __ldcs(p + slot + 256);
        float4 c = __ldcs(p + slot + 512);
        s[i] = ((a.x + a.y) + (a.z + a.w))
             + ((b.x + b.y) + (b.z + b.w))
             + ((c.x + c.y) + (c.z + c.w));
    }

    #pragma unroll
    for (int i = 0; i < 2; ++i) {
        float v = s[i];
        v += __shfl_xor_sync(0xffffffffu, v, 1);
        v += __shfl_xor_sync(0xffffffffu, v, 2);
        if ((t & 3) == 0) {
            float mean = v * (1.0f / 48.0f);
            float ang = mean * (PI_F / 255.0f) - (PI_F * 0.5f);
            __stcs(&out[(size_t)(img0 + i * 2) * 64 + (slot >> 2)], cosf(ang));
        }
    }
}

extern "C" void kernel_launch(void* const* d_in, const int* in_sizes, int n_in,
                              void* d_out, int out_size) {
    const float4* in = (const float4*)d_in[0];
    float* out = (float*)d_out;
    int n_img = in_sizes[0] / (3 * 32 * 32);     // 32768
    int blocks = n_img / 4;                      // 8192
    qae_kernel<<<blocks, 512>>>(in, out);
}